// round 15
// baseline (speedup 1.0000x reference)
#include <cuda_runtime.h>
#include <cuda_fp16.h>
#include <cstdint>

#define BATCH    8192
#define DIM      512
#define MARGIN_F 0.3f

#define BM 128                    // i rows per tile (A resident per ib)
#define BN 256                    // j cols per tile
#define BK 64                     // k per B chunk
#define NKC (DIM / BK)            // 8
#define NJT (BATCH / BN)          // 32
#define NTILES 1056               // sum_{ib<64} (32 - ib/2)
#define NTHR 256

// A: resident 128 rows x 512 halves (+8 pad) = 260 words/row (260%32==4).
// B: staged   256 rows x 64 halves (+8 pad)  = 36 words/row  (36%32==4).
// bank start = 4*row mod 32 -> ldmatrix conflict-free.
#define ASTR_W 260
#define BSTR_W 36
#define A_BYTES (BM * ASTR_W * 4)            // 133120
#define B_STAGE_BYTES (BN * BSTR_W * 4)      // 36864
#define OFF_SQNT 0
#define OFF_LABT 1024
#define OFF_A    2048
#define OFF_B    (OFF_A + A_BYTES)           // 135168
#define SMEM_BYTES (OFF_B + 2 * B_STAGE_BYTES)  // 208896 (proven-safe)

// device scratch
__device__ __half g_xh[BATCH * DIM];     // fp16 embeddings
__device__ float  g_sqn[BATCH];
__device__ int    g_lab[BATCH];
__device__ int    g_hp2[BATCH];          // float bits (d2 >= 0 -> int-monotone)
__device__ int    g_hn2[BATCH];
__device__ int    g_done;                // last-block-done counter

__device__ __forceinline__ uint32_t smem_u32(const void* p) {
    uint32_t a;
    asm("{ .reg .u64 t; cvta.to.shared.u64 t, %1; cvt.u32.u64 %0, t; }"
        : "=r"(a) : "l"(p));
    return a;
}
__device__ __forceinline__ void cp16(uint32_t saddr, const void* gptr) {
    asm volatile("cp.async.cg.shared.global [%0], [%1], 16;"
                 :: "r"(saddr), "l"(gptr) : "memory");
}
__device__ __forceinline__ void ldsm4(uint32_t* r, uint32_t addr) {
    asm volatile("ldmatrix.sync.aligned.m8n8.x4.shared.b16 {%0,%1,%2,%3}, [%4];"
                 : "=r"(r[0]), "=r"(r[1]), "=r"(r[2]), "=r"(r[3]) : "r"(addr));
}
// fp16-accumulate MMA: D,C are 2 b32 regs (4 halves). Layout matches the
// fp32-acc register positions: c0 = {row r, cols c,c+1}, c1 = {row r+8, ...}.
__device__ __forceinline__ void mma_f16acc(uint32_t* c, const uint32_t* a,
                                           const uint32_t* b) {
    asm volatile(
        "mma.sync.aligned.m16n8k16.row.col.f16.f16.f16.f16 "
        "{%0,%1}, {%2,%3,%4,%5}, {%6,%7}, {%0,%1};"
        : "+r"(c[0]), "+r"(c[1])
        : "r"(a[0]), "r"(a[1]), "r"(a[2]), "r"(a[3]), "r"(b[0]), "r"(b[1]));
}
__device__ __forceinline__ void promote(float* a, const uint32_t* c) {
    float2 f0 = __half22float2(*reinterpret_cast<const __half2*>(&c[0]));
    float2 f1 = __half22float2(*reinterpret_cast<const __half2*>(&c[1]));
    a[0] += f0.x; a[1] += f0.y; a[2] += f1.x; a[3] += f1.y;
}

// ---------------------------------------------------------------------------
// Prep: fp16 conversion, fp32 squared norms, labels, init, counter reset.
// ---------------------------------------------------------------------------
__global__ void prep_kernel(const float* __restrict__ x,
                            const int* __restrict__ lab) {
    int row  = blockIdx.x * 8 + (threadIdx.x >> 5);
    int lane = threadIdx.x & 31;
    const float4* xr = reinterpret_cast<const float4*>(x + (size_t)row * DIM);
    float s = 0.f;
    #pragma unroll
    for (int it = 0; it < 4; it++) {
        int c = lane + it * 32;
        float4 v = xr[c];
        s += v.x * v.x + v.y * v.y + v.z * v.z + v.w * v.w;
        __half2 h0 = __floats2half2_rn(v.x, v.y);
        __half2 h1 = __floats2half2_rn(v.z, v.w);
        *reinterpret_cast<__half2*>(&g_xh[row * DIM + c * 4])     = h0;
        *reinterpret_cast<__half2*>(&g_xh[row * DIM + c * 4 + 2]) = h1;
    }
    #pragma unroll
    for (int o = 16; o; o >>= 1) s += __shfl_xor_sync(0xffffffffu, s, o);
    if (lane == 0) {
        g_sqn[row] = s;
        g_lab[row] = lab[row];
        g_hp2[row] = -1;           // sentinel: no positive
        g_hn2[row] = 0x7f800000;   // +inf: no negative
        if (row == 0) g_done = 0;
    }
}

// ---------------------------------------------------------------------------
// Main: R14 structure; inner accumulation switched to f16-acc HMMA with
// per-chunk (K=64) promotion into the fp32 master accumulator.
// ---------------------------------------------------------------------------
__global__ void __launch_bounds__(NTHR, 1) triplet_sym(float* __restrict__ out) {
    extern __shared__ char smem[];
    float* sqnT = reinterpret_cast<float*>(smem + OFF_SQNT);   // 256
    int*   labT = reinterpret_cast<int*>(smem + OFF_LABT);

    const uint32_t sA = smem_u32(smem + OFF_A);
    const uint32_t sB = smem_u32(smem + OFF_B);

    const int tid  = threadIdx.x;
    const int lane = tid & 31;
    const int wid  = tid >> 5;
    const int wr   = wid & 1;        // row half (64 rows)
    const int wc   = wid >> 1;       // col quarter (64 cols)
    const int qrow = lane >> 2;
    const int qcol = lane & 3;
    const int lrow = lane & 15, lksel = lane >> 4;

    const uint32_t tbeg = (uint32_t)(((uint64_t)blockIdx.x * NTILES) / gridDim.x);
    const uint32_t tend = (uint32_t)(((uint64_t)(blockIdx.x + 1) * NTILES) / gridDim.x);

    if (tbeg < tend) {
        int ib, jt;
        {
            uint32_t rem = tbeg;
            int b = 0;
            while (rem >= (uint32_t)(NJT - (b >> 1))) {
                rem -= (uint32_t)(NJT - (b >> 1));
                b++;
            }
            ib = b;
            jt = (b >> 1) + (int)rem;
        }

        uint32_t bAddr[4];
        #pragma unroll
        for (int f = 0; f < 4; f++)
            bAddr[f] = sB + ((wc * 64 + f * 16 + lrow) * BSTR_W + 4 * lksel) * 4;

        int cur_ib = -1, i0 = 0;
        float sqi[4][2];
        int   li [4][2];
        uint32_t aAddr[4];
        float acc[4][8][4];

        auto load_B = [&](int j0_, int kc_, int s_) {
            const int k0 = kc_ * BK;
            const uint32_t bbase = sB + (uint32_t)s_ * B_STAGE_BYTES;
            #pragma unroll
            for (int it = 0; it < 8; it++) {
                int seg = tid + it * NTHR;       // 2048 segs: 256 rows x 8
                int n = seg >> 3, sc = seg & 7;
                cp16(bbase + (n * BSTR_W + sc * 4) * 4,
                     g_xh + (j0_ + n) * DIM + k0 + sc * 8);
            }
            asm volatile("cp.async.commit_group;" ::: "memory");
        };

        for (uint32_t t = tbeg; t < tend; t++) {
            const int j0 = jt * BN;
            const bool nextSame = (t + 1 < tend) && (jt + 1 < NJT);

            if (ib != cur_ib) {
                cur_ib = ib;
                i0 = ib * BM;
                #pragma unroll
                for (int it = 0; it < 32; it++) {   // A: 8192 segs
                    int seg = tid + it * NTHR;
                    int m = seg >> 6, sc = seg & 63;
                    cp16(sA + (m * ASTR_W + sc * 4) * 4,
                         g_xh + (i0 + m) * DIM + sc * 8);
                }
                asm volatile("cp.async.commit_group;" ::: "memory");
                #pragma unroll
                for (int mf = 0; mf < 4; mf++)
                    #pragma unroll
                    for (int rh = 0; rh < 2; rh++) {
                        int r = i0 + wr * 64 + mf * 16 + qrow + rh * 8;
                        sqi[mf][rh] = g_sqn[r];
                        li [mf][rh] = g_lab[r];
                    }
                #pragma unroll
                for (int mf = 0; mf < 4; mf++)
                    aAddr[mf] = sA + ((wr * 64 + mf * 16 + lrow) * ASTR_W
                                      + 4 * lksel) * 4;
                load_B(j0, 0, 0);
            }

            for (int kc = 0; kc < NKC; kc++) {
                if (kc + 1 < NKC) {
                    load_B(j0, kc + 1, (kc + 1) & 1);
                    asm volatile("cp.async.wait_group 1;" ::: "memory");
                } else if (nextSame) {
                    load_B(j0 + BN, 0, 0);     // cross-tile prefetch (buf 0)
                    asm volatile("cp.async.wait_group 1;" ::: "memory");
                } else {
                    asm volatile("cp.async.wait_group 0;" ::: "memory");
                }
                if (kc == 0) {
                    sqnT[tid] = g_sqn[j0 + tid];
                    labT[tid] = g_lab[j0 + tid];
                }
                __syncthreads();

                if (kc == 0) {
                    #pragma unroll
                    for (int mf = 0; mf < 4; mf++)
                        #pragma unroll
                        for (int nf = 0; nf < 8; nf++)
                            #pragma unroll
                            for (int q = 0; q < 4; q++) acc[mf][nf][q] = 0.f;
                }

                const uint32_t aOff = (uint32_t)kc * 128u;
                const uint32_t bOff = (uint32_t)(kc & 1) * B_STAGE_BYTES;

                // f16 working accumulators for this K=64 chunk
                uint32_t acc16[4][8][2];
                #pragma unroll
                for (int mf = 0; mf < 4; mf++)
                    #pragma unroll
                    for (int nf = 0; nf < 8; nf++) {
                        acc16[mf][nf][0] = 0u;
                        acc16[mf][nf][1] = 0u;
                    }

                #pragma unroll
                for (int ks = 0; ks < 4; ks++) {             // 4 x k16 = BK
                    const uint32_t kB = (uint32_t)ks * 32u;
                    uint32_t af[4][4], bf[8][2];
                    #pragma unroll
                    for (int mf = 0; mf < 4; mf++)
                        ldsm4(af[mf], aAddr[mf] + aOff + kB);
                    #pragma unroll
                    for (int f = 0; f < 4; f++) {
                        uint32_t t4[4];
                        ldsm4(t4, bAddr[f] + bOff + kB);
                        bf[2*f  ][0] = t4[0]; bf[2*f+1][0] = t4[1];
                        bf[2*f  ][1] = t4[2]; bf[2*f+1][1] = t4[3];
                    }
                    #pragma unroll
                    for (int mf = 0; mf < 4; mf++)
                        #pragma unroll
                        for (int nf = 0; nf < 8; nf++)
                            mma_f16acc(acc16[mf][nf], af[mf], bf[nf]);
                }

                // promote chunk partials into fp32 master (FMA pipe, overlaps)
                #pragma unroll
                for (int mf = 0; mf < 4; mf++)
                    #pragma unroll
                    for (int nf = 0; nf < 8; nf++)
                        promote(acc[mf][nf], acc16[mf][nf]);

                if (kc == NKC - 1) {
                    // ---- two-sided mining epilogue ----
                    const float INF = __int_as_float(0x7f800000);
                    float hpr[4][2], hnr[4][2];
                    #pragma unroll
                    for (int mf = 0; mf < 4; mf++)
                        #pragma unroll
                        for (int rh = 0; rh < 2; rh++) {
                            hpr[mf][rh] = -1.0f; hnr[mf][rh] = INF;
                        }
                    #pragma unroll
                    for (int nf = 0; nf < 8; nf++) {
                        const int jl  = wc * 64 + nf * 8 + qcol * 2;
                        const int jg0 = j0 + jl, jg1 = jg0 + 1;
                        const float sqj0 = sqnT[jl], sqj1 = sqnT[jl + 1];
                        const int   lj0  = labT[jl], lj1  = labT[jl + 1];
                        float hpc0 = -1.f, hnc0 = INF, hpc1 = -1.f, hnc1 = INF;
                        #pragma unroll
                        for (int mf = 0; mf < 4; mf++)
                            #pragma unroll
                            for (int rh = 0; rh < 2; rh++) {
                                const int irow = i0 + wr * 64 + mf * 16
                                                 + qrow + rh * 8;
                                float d20 = fmaxf(fmaf(-2.f, acc[mf][nf][rh*2+0],
                                                       sqi[mf][rh] + sqj0), 0.f);
                                float d21 = fmaxf(fmaf(-2.f, acc[mf][nf][rh*2+1],
                                                       sqi[mf][rh] + sqj1), 0.f);
                                if (lj0 == li[mf][rh]) {
                                    if (jg0 != irow) {
                                        hpr[mf][rh] = fmaxf(hpr[mf][rh], d20);
                                        hpc0 = fmaxf(hpc0, d20);
                                    }
                                } else {
                                    hnr[mf][rh] = fminf(hnr[mf][rh], d20);
                                    hnc0 = fminf(hnc0, d20);
                                }
                                if (lj1 == li[mf][rh]) {
                                    if (jg1 != irow) {
                                        hpr[mf][rh] = fmaxf(hpr[mf][rh], d21);
                                        hpc1 = fmaxf(hpc1, d21);
                                    }
                                } else {
                                    hnr[mf][rh] = fminf(hnr[mf][rh], d21);
                                    hnc1 = fminf(hnc1, d21);
                                }
                            }
                        #pragma unroll
                        for (int off = 4; off <= 16; off <<= 1) {
                            hpc0 = fmaxf(hpc0, __shfl_xor_sync(0xffffffffu, hpc0, off));
                            hnc0 = fminf(hnc0, __shfl_xor_sync(0xffffffffu, hnc0, off));
                            hpc1 = fmaxf(hpc1, __shfl_xor_sync(0xffffffffu, hpc1, off));
                            hnc1 = fminf(hnc1, __shfl_xor_sync(0xffffffffu, hnc1, off));
                        }
                        if (qrow == 0) {
                            atomicMax(&g_hp2[jg0], __float_as_int(hpc0));
                            atomicMin(&g_hn2[jg0], __float_as_int(hnc0));
                            atomicMax(&g_hp2[jg1], __float_as_int(hpc1));
                            atomicMin(&g_hn2[jg1], __float_as_int(hnc1));
                        }
                    }
                    #pragma unroll
                    for (int mf = 0; mf < 4; mf++)
                        #pragma unroll
                        for (int rh = 0; rh < 2; rh++) {
                            float hp = hpr[mf][rh], hn = hnr[mf][rh];
                            hp = fmaxf(hp, __shfl_xor_sync(0xffffffffu, hp, 1));
                            hp = fmaxf(hp, __shfl_xor_sync(0xffffffffu, hp, 2));
                            hn = fminf(hn, __shfl_xor_sync(0xffffffffu, hn, 1));
                            hn = fminf(hn, __shfl_xor_sync(0xffffffffu, hn, 2));
                            if (qcol == 0) {
                                int r = i0 + wr * 64 + mf * 16 + qrow + rh * 8;
                                atomicMax(&g_hp2[r], __float_as_int(hp));
                                atomicMin(&g_hn2[r], __float_as_int(hn));
                            }
                        }
                }
                __syncthreads();
            }

            jt++;
            if (jt == NJT) { ib++; jt = ib >> 1; }
        }
    }

    // ---- fused final reduce: last block to finish computes the mean ----
    {
        __shared__ int sLast;
        const int tid2 = threadIdx.x;
        __threadfence();
        __syncthreads();
        if (tid2 == 0) sLast = (atomicAdd(&g_done, 1) == (int)gridDim.x - 1);
        __syncthreads();
        if (sLast) {
            __shared__ float ss[NTHR];
            __shared__ int   sc[NTHR];
            float lsum = 0.f; int lcnt = 0;
            for (int r = tid2; r < BATCH; r += NTHR) {
                int hp = g_hp2[r], hn = g_hn2[r];
                if (hp >= 0 && hn < 0x7f800000) {
                    float l = sqrtf(__int_as_float(hp) + 1e-16f)
                            - sqrtf(__int_as_float(hn) + 1e-16f) + MARGIN_F;
                    lsum += fmaxf(l, 0.f);
                    lcnt += 1;
                }
            }
            ss[tid2] = lsum; sc[tid2] = lcnt;
            __syncthreads();
            for (int o = NTHR / 2; o; o >>= 1) {
                if (tid2 < o) { ss[tid2] += ss[tid2 + o]; sc[tid2] += sc[tid2 + o]; }
                __syncthreads();
            }
            if (tid2 == 0) out[0] = ss[0] / fmaxf((float)sc[0], 1.f);
        }
    }
}

extern "C" void kernel_launch(void* const* d_in, const int* in_sizes, int n_in,
                              void* d_out, int out_size) {
    const float* x   = (const float*)d_in[0];
    const int*   lab = (const int*)d_in[1];   // JAX x64-disabled: int32 labels
    float*       out = (float*)d_out;

    static int nsm = 0;
    if (nsm == 0) {
        int dev = 0;
        cudaGetDevice(&dev);
        if (cudaDeviceGetAttribute(&nsm, cudaDevAttrMultiProcessorCount, dev)
            != cudaSuccess || nsm < 1 || nsm > NTILES)
            nsm = 148;
    }

    cudaFuncSetAttribute(triplet_sym,
                         cudaFuncAttributeMaxDynamicSharedMemorySize, SMEM_BYTES);

    prep_kernel<<<BATCH / 8, 256>>>(x, lab);
    triplet_sym<<<nsm, NTHR, SMEM_BYTES>>>(out);
}

// round 16
// speedup vs baseline: 1.1715x; 1.1715x over previous
#include <cuda_runtime.h>
#include <cuda_fp16.h>
#include <cstdint>

#define BATCH    8192
#define DIM      512
#define MARGIN_F 0.3f

#define BM 128                    // i rows per tile (A resident per ib)
#define BN 256                    // j cols per tile
#define BK 64                     // k per B chunk
#define NKC (DIM / BK)            // 8
#define NJT (BATCH / BN)          // 32
#define NTILES 1056               // sum_{ib<64} (32 - ib/2)

// A: resident 128 rows x 512 halves (+8 pad) = 260 words/row (260%32==4).
// B: staged   256 rows x 64 halves (+8 pad)  = 36 words/row  (36%32==4).
// bank start = 4*row mod 32 -> ldmatrix conflict-free.
#define ASTR_W 260
#define BSTR_W 36
#define A_BYTES (BM * ASTR_W * 4)            // 133120
#define B_STAGE_BYTES (BN * BSTR_W * 4)      // 36864
#define OFF_SQNT 0
#define OFF_LABT 1024
#define OFF_A    2048
#define OFF_B    (OFF_A + A_BYTES)           // 135168
#define SMEM_BYTES (OFF_B + 2 * B_STAGE_BYTES)  // 208896

// device scratch
__device__ __half g_xh[BATCH * DIM];     // fp16 embeddings
__device__ float  g_sqn[BATCH];
__device__ int    g_lab[BATCH];
__device__ int    g_hp2[BATCH];          // float bits (d2 >= 0 -> int-monotone)
__device__ int    g_hn2[BATCH];

__device__ __forceinline__ uint32_t smem_u32(const void* p) {
    uint32_t a;
    asm("{ .reg .u64 t; cvta.to.shared.u64 t, %1; cvt.u32.u64 %0, t; }"
        : "=r"(a) : "l"(p));
    return a;
}
__device__ __forceinline__ void cp16(uint32_t saddr, const void* gptr) {
    asm volatile("cp.async.cg.shared.global [%0], [%1], 16;"
                 :: "r"(saddr), "l"(gptr) : "memory");
}
__device__ __forceinline__ void ldsm4(uint32_t* r, uint32_t addr) {
    asm volatile("ldmatrix.sync.aligned.m8n8.x4.shared.b16 {%0,%1,%2,%3}, [%4];"
                 : "=r"(r[0]), "=r"(r[1]), "=r"(r[2]), "=r"(r[3]) : "r"(addr));
}
__device__ __forceinline__ void mma_fp16(float* c, const uint32_t* a,
                                         const uint32_t* b) {
    asm volatile(
        "mma.sync.aligned.m16n8k16.row.col.f32.f16.f16.f32 "
        "{%0,%1,%2,%3}, {%4,%5,%6,%7}, {%8,%9}, {%0,%1,%2,%3};"
        : "+f"(c[0]), "+f"(c[1]), "+f"(c[2]), "+f"(c[3])
        : "r"(a[0]), "r"(a[1]), "r"(a[2]), "r"(a[3]), "r"(b[0]), "r"(b[1]));
}

// ---------------------------------------------------------------------------
// Prep: fp16 conversion, fp32 squared norms, labels, mining-array init.
// ---------------------------------------------------------------------------
__global__ void prep_kernel(const float* __restrict__ x,
                            const int* __restrict__ lab) {
    int row  = blockIdx.x * 8 + (threadIdx.x >> 5);
    int lane = threadIdx.x & 31;
    const float4* xr = reinterpret_cast<const float4*>(x + (size_t)row * DIM);
    float s = 0.f;
    #pragma unroll
    for (int it = 0; it < 4; it++) {
        int c = lane + it * 32;
        float4 v = xr[c];
        s += v.x * v.x + v.y * v.y + v.z * v.z + v.w * v.w;
        __half2 h0 = __floats2half2_rn(v.x, v.y);
        __half2 h1 = __floats2half2_rn(v.z, v.w);
        *reinterpret_cast<__half2*>(&g_xh[row * DIM + c * 4])     = h0;
        *reinterpret_cast<__half2*>(&g_xh[row * DIM + c * 4 + 2]) = h1;
    }
    #pragma unroll
    for (int o = 16; o; o >>= 1) s += __shfl_xor_sync(0xffffffffu, s, o);
    if (lane == 0) {
        g_sqn[row] = s;
        g_lab[row] = lab[row];
        g_hp2[row] = -1;           // sentinel: no positive
        g_hn2[row] = 0x7f800000;   // +inf: no negative
    }
}

// ---------------------------------------------------------------------------
// Main: symmetric fp16 mma.sync Gram + two-sided hard mining.
// Tile set: (ib, jt) with jt >= ib/2 (1056 tiles); contiguous static ranges
// per block; ib-major order keeps A resident.
// ---------------------------------------------------------------------------
__global__ void __launch_bounds__(256, 1) triplet_sym() {
    extern __shared__ char smem[];
    float* sqnT = reinterpret_cast<float*>(smem + OFF_SQNT);   // 256
    int*   labT = reinterpret_cast<int*>(smem + OFF_LABT);

    const uint32_t sA = smem_u32(smem + OFF_A);
    const uint32_t sB = smem_u32(smem + OFF_B);

    const int tid  = threadIdx.x;
    const int lane = tid & 31;
    const int wid  = tid >> 5;
    const int wr   = wid & 1;        // row half
    const int wc   = wid >> 1;       // col quarter
    const int qrow = lane >> 2;
    const int qcol = lane & 3;
    const int lrow = lane & 15, lksel = lane >> 4;

    const uint32_t tbeg = (uint32_t)(((uint64_t)blockIdx.x * NTILES) / gridDim.x);
    const uint32_t tend = (uint32_t)(((uint64_t)(blockIdx.x + 1) * NTILES) / gridDim.x);
    if (tbeg >= tend) return;

    // decode tbeg -> (ib, jt); count(ib) = NJT - ib/2, jt starts at ib/2
    int ib, jt;
    {
        uint32_t rem = tbeg;
        int b = 0;
        while (rem >= (uint32_t)(NJT - (b >> 1))) {
            rem -= (uint32_t)(NJT - (b >> 1));
            b++;
        }
        ib = b;
        jt = (b >> 1) + (int)rem;
    }

    uint32_t bAddr[4];
    #pragma unroll
    for (int f = 0; f < 4; f++)
        bAddr[f] = sB + ((wc * 64 + f * 16 + lrow) * BSTR_W + 4 * lksel) * 4;

    int cur_ib = -1, i0 = 0;
    float sqi[4][2];
    int   li [4][2];
    uint32_t aAddr[4];
    float acc[4][8][4];

    auto load_B = [&](int j0_, int kc_, int s_) {
        const int k0 = kc_ * BK;
        const uint32_t bbase = sB + (uint32_t)s_ * B_STAGE_BYTES;
        #pragma unroll
        for (int it = 0; it < 8; it++) {
            int seg = tid + it * 256;
            int n = seg >> 3, sc = seg & 7;
            cp16(bbase + (n * BSTR_W + sc * 4) * 4,
                 g_xh + (j0_ + n) * DIM + k0 + sc * 8);
        }
        asm volatile("cp.async.commit_group;" ::: "memory");
    };

    for (uint32_t t = tbeg; t < tend; t++) {
        const int j0 = jt * BN;

        if (ib != cur_ib) {
            // previous tile's mma/ldsm done (trailing __syncthreads); safe to
            // overwrite A. Committed as its own cp.async group BEFORE B0.
            cur_ib = ib;
            i0 = ib * BM;
            #pragma unroll
            for (int it = 0; it < 32; it++) {
                int seg = tid + it * 256;
                int m = seg >> 6, sc = seg & 63;
                cp16(sA + (m * ASTR_W + sc * 4) * 4,
                     g_xh + (i0 + m) * DIM + sc * 8);
            }
            asm volatile("cp.async.commit_group;" ::: "memory");
            #pragma unroll
            for (int mf = 0; mf < 4; mf++)
                #pragma unroll
                for (int rh = 0; rh < 2; rh++) {
                    int r = i0 + wr * 64 + mf * 16 + qrow + rh * 8;
                    sqi[mf][rh] = g_sqn[r];
                    li [mf][rh] = g_lab[r];
                }
            #pragma unroll
            for (int mf = 0; mf < 4; mf++)
                aAddr[mf] = sA + ((wr * 64 + mf * 16 + lrow) * ASTR_W
                                  + 4 * lksel) * 4;
        }

        load_B(j0, 0, 0);

        for (int kc = 0; kc < NKC; kc++) {
            if (kc + 1 < NKC) {
                load_B(j0, kc + 1, (kc + 1) & 1);
                asm volatile("cp.async.wait_group 1;" ::: "memory");
            } else {
                asm volatile("cp.async.wait_group 0;" ::: "memory");
            }
            if (kc == 0) {
                sqnT[tid] = g_sqn[j0 + tid];    // prev epilogue readers done
                labT[tid] = g_lab[j0 + tid];    // (trailing sync of prev tile)
            }
            __syncthreads();

            if (kc == 0) {
                #pragma unroll
                for (int mf = 0; mf < 4; mf++)
                    #pragma unroll
                    for (int nf = 0; nf < 8; nf++)
                        #pragma unroll
                        for (int q = 0; q < 4; q++) acc[mf][nf][q] = 0.f;
            }

            const uint32_t aOff = (uint32_t)kc * 128u;    // kc*32 words *4B
            const uint32_t bOff = (uint32_t)(kc & 1) * B_STAGE_BYTES;

            #pragma unroll
            for (int ks = 0; ks < 4; ks++) {              // 4 x k16 = BK
                const uint32_t kB = (uint32_t)ks * 32u;
                uint32_t af[4][4], bf[8][2];
                #pragma unroll
                for (int mf = 0; mf < 4; mf++)
                    ldsm4(af[mf], aAddr[mf] + aOff + kB);
                #pragma unroll
                for (int f = 0; f < 4; f++) {
                    uint32_t t4[4];
                    ldsm4(t4, bAddr[f] + bOff + kB);
                    bf[2*f  ][0] = t4[0]; bf[2*f+1][0] = t4[1];
                    bf[2*f  ][1] = t4[2]; bf[2*f+1][1] = t4[3];
                }
                #pragma unroll
                for (int mf = 0; mf < 4; mf++)
                    #pragma unroll
                    for (int nf = 0; nf < 8; nf++)
                        mma_fp16(acc[mf][nf], af[mf], bf[nf]);
            }

            if (kc == NKC - 1) {
                // ---- two-sided mining epilogue ----
                const float INF = __int_as_float(0x7f800000);
                float hpr[4][2], hnr[4][2];
                #pragma unroll
                for (int mf = 0; mf < 4; mf++)
                    #pragma unroll
                    for (int rh = 0; rh < 2; rh++) {
                        hpr[mf][rh] = -1.0f; hnr[mf][rh] = INF;
                    }
                #pragma unroll
                for (int nf = 0; nf < 8; nf++) {
                    const int jl  = wc * 64 + nf * 8 + qcol * 2;
                    const int jg0 = j0 + jl, jg1 = jg0 + 1;
                    const float sqj0 = sqnT[jl], sqj1 = sqnT[jl + 1];
                    const int   lj0  = labT[jl], lj1  = labT[jl + 1];
                    float hpc0 = -1.f, hnc0 = INF, hpc1 = -1.f, hnc1 = INF;
                    #pragma unroll
                    for (int mf = 0; mf < 4; mf++)
                        #pragma unroll
                        for (int rh = 0; rh < 2; rh++) {
                            const int irow = i0 + wr * 64 + mf * 16
                                             + qrow + rh * 8;
                            float d20 = fmaxf(fmaf(-2.f, acc[mf][nf][rh*2+0],
                                                   sqi[mf][rh] + sqj0), 0.f);
                            float d21 = fmaxf(fmaf(-2.f, acc[mf][nf][rh*2+1],
                                                   sqi[mf][rh] + sqj1), 0.f);
                            if (lj0 == li[mf][rh]) {
                                if (jg0 != irow) {
                                    hpr[mf][rh] = fmaxf(hpr[mf][rh], d20);
                                    hpc0 = fmaxf(hpc0, d20);
                                }
                            } else {
                                hnr[mf][rh] = fminf(hnr[mf][rh], d20);
                                hnc0 = fminf(hnc0, d20);
                            }
                            if (lj1 == li[mf][rh]) {
                                if (jg1 != irow) {
                                    hpr[mf][rh] = fmaxf(hpr[mf][rh], d21);
                                    hpc1 = fmaxf(hpc1, d21);
                                }
                            } else {
                                hnr[mf][rh] = fminf(hnr[mf][rh], d21);
                                hnc1 = fminf(hnc1, d21);
                            }
                        }
                    // column-side reduce across qrow lanes
                    #pragma unroll
                    for (int off = 4; off <= 16; off <<= 1) {
                        hpc0 = fmaxf(hpc0, __shfl_xor_sync(0xffffffffu, hpc0, off));
                        hnc0 = fminf(hnc0, __shfl_xor_sync(0xffffffffu, hnc0, off));
                        hpc1 = fmaxf(hpc1, __shfl_xor_sync(0xffffffffu, hpc1, off));
                        hnc1 = fminf(hnc1, __shfl_xor_sync(0xffffffffu, hnc1, off));
                    }
                    if (qrow == 0) {
                        atomicMax(&g_hp2[jg0], __float_as_int(hpc0));
                        atomicMin(&g_hn2[jg0], __float_as_int(hnc0));
                        atomicMax(&g_hp2[jg1], __float_as_int(hpc1));
                        atomicMin(&g_hn2[jg1], __float_as_int(hnc1));
                    }
                }
                // row-side reduce across qcol lanes
                #pragma unroll
                for (int mf = 0; mf < 4; mf++)
                    #pragma unroll
                    for (int rh = 0; rh < 2; rh++) {
                        float hp = hpr[mf][rh], hn = hnr[mf][rh];
                        hp = fmaxf(hp, __shfl_xor_sync(0xffffffffu, hp, 1));
                        hp = fmaxf(hp, __shfl_xor_sync(0xffffffffu, hp, 2));
                        hn = fminf(hn, __shfl_xor_sync(0xffffffffu, hn, 1));
                        hn = fminf(hn, __shfl_xor_sync(0xffffffffu, hn, 2));
                        if (qcol == 0) {
                            int r = i0 + wr * 64 + mf * 16 + qrow + rh * 8;
                            atomicMax(&g_hp2[r], __float_as_int(hp));
                            atomicMin(&g_hn2[r], __float_as_int(hn));
                        }
                    }
            }
            __syncthreads();
        }

        // advance to next tile (ib-major order keeps A resident)
        jt++;
        if (jt == NJT) { ib++; jt = ib >> 1; }
    }
}

// ---------------------------------------------------------------------------
// Final reduce: per-row loss, masked mean.
// ---------------------------------------------------------------------------
__global__ void reduce_kernel(float* __restrict__ out) {
    __shared__ float ss[1024];
    __shared__ int   sc[1024];
    const int t = threadIdx.x;
    float lsum = 0.f; int lcnt = 0;
    for (int r = t; r < BATCH; r += 1024) {
        int hp = g_hp2[r], hn = g_hn2[r];
        if (hp >= 0 && hn < 0x7f800000) {
            float l = sqrtf(__int_as_float(hp) + 1e-16f)
                    - sqrtf(__int_as_float(hn) + 1e-16f) + MARGIN_F;
            lsum += fmaxf(l, 0.f);
            lcnt += 1;
        }
    }
    ss[t] = lsum; sc[t] = lcnt;
    __syncthreads();
    for (int o = 512; o; o >>= 1) {
        if (t < o) { ss[t] += ss[t + o]; sc[t] += sc[t + o]; }
        __syncthreads();
    }
    if (t == 0) out[0] = ss[0] / fmaxf((float)sc[0], 1.f);
}

extern "C" void kernel_launch(void* const* d_in, const int* in_sizes, int n_in,
                              void* d_out, int out_size) {
    const float* x   = (const float*)d_in[0];
    const int*   lab = (const int*)d_in[1];   // JAX x64-disabled: int32 labels
    float*       out = (float*)d_out;

    static int nsm = 0;
    if (nsm == 0) {
        int dev = 0;
        cudaGetDevice(&dev);
        if (cudaDeviceGetAttribute(&nsm, cudaDevAttrMultiProcessorCount, dev)
            != cudaSuccess || nsm < 1 || nsm > NTILES)
            nsm = 148;
    }

    cudaFuncSetAttribute(triplet_sym,
                         cudaFuncAttributeMaxDynamicSharedMemorySize, SMEM_BYTES);

    prep_kernel<<<BATCH / 8, 256>>>(x, lab);
    triplet_sym<<<nsm, 256, SMEM_BYTES>>>();
    reduce_kernel<<<1, 1024>>>(out);
}

// round 17
// speedup vs baseline: 1.1717x; 1.0002x over previous
#include <cuda_runtime.h>
#include <cuda_fp16.h>
#include <cstdint>

#define BATCH    8192
#define DIM      512
#define MARGIN_F 0.3f

#define BM 128                    // i rows per tile (A resident per ib)
#define BN 256                    // j cols per tile
#define BK 64                     // k per B chunk
#define NKC (DIM / BK)            // 8
#define NJT (BATCH / BN)          // 32
#define NTILES 1056               // sum_{ib<64} (32 - ib/2)

// A: resident 128 rows x 512 halves (+8 pad) = 260 words/row (260%32==4).
// B: staged   256 rows x 64 halves (+8 pad)  = 36 words/row  (36%32==4).
// bank start = 4*row mod 32 -> ldmatrix conflict-free.
#define ASTR_W 260
#define BSTR_W 36
#define A_BYTES (BM * ASTR_W * 4)            // 133120
#define B_STAGE_BYTES (BN * BSTR_W * 4)      // 36864
#define OFF_SQNT 0
#define OFF_LABT 1024
#define OFF_A    2048
#define OFF_B    (OFF_A + A_BYTES)           // 135168
#define SMEM_BYTES (OFF_B + 2 * B_STAGE_BYTES)  // 208896

// device scratch
__device__ __half g_xh[BATCH * DIM];     // fp16 embeddings
__device__ float  g_sqn[BATCH];
__device__ int    g_lab[BATCH];
__device__ int    g_hp2[BATCH];          // float bits (d2 >= 0 -> int-monotone)
__device__ int    g_hn2[BATCH];

__device__ __forceinline__ uint32_t smem_u32(const void* p) {
    uint32_t a;
    asm("{ .reg .u64 t; cvta.to.shared.u64 t, %1; cvt.u32.u64 %0, t; }"
        : "=r"(a) : "l"(p));
    return a;
}
__device__ __forceinline__ void cp16(uint32_t saddr, const void* gptr) {
    asm volatile("cp.async.cg.shared.global [%0], [%1], 16;"
                 :: "r"(saddr), "l"(gptr) : "memory");
}
__device__ __forceinline__ void ldsm4(uint32_t* r, uint32_t addr) {
    asm volatile("ldmatrix.sync.aligned.m8n8.x4.shared.b16 {%0,%1,%2,%3}, [%4];"
                 : "=r"(r[0]), "=r"(r[1]), "=r"(r[2]), "=r"(r[3]) : "r"(addr));
}
__device__ __forceinline__ void mma_fp16(float* c, const uint32_t* a,
                                         const uint32_t* b) {
    asm volatile(
        "mma.sync.aligned.m16n8k16.row.col.f32.f16.f16.f32 "
        "{%0,%1,%2,%3}, {%4,%5,%6,%7}, {%8,%9}, {%0,%1,%2,%3};"
        : "+f"(c[0]), "+f"(c[1]), "+f"(c[2]), "+f"(c[3])
        : "r"(a[0]), "r"(a[1]), "r"(a[2]), "r"(a[3]), "r"(b[0]), "r"(b[1]));
}

// ---------------------------------------------------------------------------
// Prep: fp16 conversion, fp32 squared norms, labels, mining-array init.
// One warp per TWO rows; all 8 float4 loads issued before any math (MLP=8)
// to halve exposed DRAM latency vs the MLP=4 one-row version.
// ---------------------------------------------------------------------------
__global__ void prep_kernel(const float* __restrict__ x,
                            const int* __restrict__ lab) {
    int warp = blockIdx.x * 8 + (threadIdx.x >> 5);
    int lane = threadIdx.x & 31;
    int row0 = warp * 2;

    float4 v[2][4];
    #pragma unroll
    for (int r = 0; r < 2; r++) {
        const float4* xr =
            reinterpret_cast<const float4*>(x + (size_t)(row0 + r) * DIM);
        #pragma unroll
        for (int it = 0; it < 4; it++)
            v[r][it] = xr[lane + it * 32];
    }

    #pragma unroll
    for (int r = 0; r < 2; r++) {
        int row = row0 + r;
        float s = 0.f;
        #pragma unroll
        for (int it = 0; it < 4; it++) {
            float4 q = v[r][it];
            s += q.x * q.x + q.y * q.y + q.z * q.z + q.w * q.w;
            int c = lane + it * 32;
            __half2 h0 = __floats2half2_rn(q.x, q.y);
            __half2 h1 = __floats2half2_rn(q.z, q.w);
            *reinterpret_cast<__half2*>(&g_xh[row * DIM + c * 4])     = h0;
            *reinterpret_cast<__half2*>(&g_xh[row * DIM + c * 4 + 2]) = h1;
        }
        #pragma unroll
        for (int o = 16; o; o >>= 1) s += __shfl_xor_sync(0xffffffffu, s, o);
        if (lane == 0) {
            g_sqn[row] = s;
            g_lab[row] = lab[row];
            g_hp2[row] = -1;           // sentinel: no positive
            g_hn2[row] = 0x7f800000;   // +inf: no negative
        }
    }
}

// ---------------------------------------------------------------------------
// Main: symmetric fp16 mma.sync Gram + two-sided hard mining.
// Tile set: (ib, jt) with jt >= ib/2 (1056 tiles); contiguous static ranges
// per block; ib-major order keeps A resident.   (BYTE-IDENTICAL to the
// measured 141.8us optimum — do not modify.)
// ---------------------------------------------------------------------------
__global__ void __launch_bounds__(256, 1) triplet_sym() {
    extern __shared__ char smem[];
    float* sqnT = reinterpret_cast<float*>(smem + OFF_SQNT);   // 256
    int*   labT = reinterpret_cast<int*>(smem + OFF_LABT);

    const uint32_t sA = smem_u32(smem + OFF_A);
    const uint32_t sB = smem_u32(smem + OFF_B);

    const int tid  = threadIdx.x;
    const int lane = tid & 31;
    const int wid  = tid >> 5;
    const int wr   = wid & 1;        // row half
    const int wc   = wid >> 1;       // col quarter
    const int qrow = lane >> 2;
    const int qcol = lane & 3;
    const int lrow = lane & 15, lksel = lane >> 4;

    const uint32_t tbeg = (uint32_t)(((uint64_t)blockIdx.x * NTILES) / gridDim.x);
    const uint32_t tend = (uint32_t)(((uint64_t)(blockIdx.x + 1) * NTILES) / gridDim.x);
    if (tbeg >= tend) return;

    // decode tbeg -> (ib, jt); count(ib) = NJT - ib/2, jt starts at ib/2
    int ib, jt;
    {
        uint32_t rem = tbeg;
        int b = 0;
        while (rem >= (uint32_t)(NJT - (b >> 1))) {
            rem -= (uint32_t)(NJT - (b >> 1));
            b++;
        }
        ib = b;
        jt = (b >> 1) + (int)rem;
    }

    uint32_t bAddr[4];
    #pragma unroll
    for (int f = 0; f < 4; f++)
        bAddr[f] = sB + ((wc * 64 + f * 16 + lrow) * BSTR_W + 4 * lksel) * 4;

    int cur_ib = -1, i0 = 0;
    float sqi[4][2];
    int   li [4][2];
    uint32_t aAddr[4];
    float acc[4][8][4];

    auto load_B = [&](int j0_, int kc_, int s_) {
        const int k0 = kc_ * BK;
        const uint32_t bbase = sB + (uint32_t)s_ * B_STAGE_BYTES;
        #pragma unroll
        for (int it = 0; it < 8; it++) {
            int seg = tid + it * 256;
            int n = seg >> 3, sc = seg & 7;
            cp16(bbase + (n * BSTR_W + sc * 4) * 4,
                 g_xh + (j0_ + n) * DIM + k0 + sc * 8);
        }
        asm volatile("cp.async.commit_group;" ::: "memory");
    };

    for (uint32_t t = tbeg; t < tend; t++) {
        const int j0 = jt * BN;

        if (ib != cur_ib) {
            cur_ib = ib;
            i0 = ib * BM;
            #pragma unroll
            for (int it = 0; it < 32; it++) {
                int seg = tid + it * 256;
                int m = seg >> 6, sc = seg & 63;
                cp16(sA + (m * ASTR_W + sc * 4) * 4,
                     g_xh + (i0 + m) * DIM + sc * 8);
            }
            asm volatile("cp.async.commit_group;" ::: "memory");
            #pragma unroll
            for (int mf = 0; mf < 4; mf++)
                #pragma unroll
                for (int rh = 0; rh < 2; rh++) {
                    int r = i0 + wr * 64 + mf * 16 + qrow + rh * 8;
                    sqi[mf][rh] = g_sqn[r];
                    li [mf][rh] = g_lab[r];
                }
            #pragma unroll
            for (int mf = 0; mf < 4; mf++)
                aAddr[mf] = sA + ((wr * 64 + mf * 16 + lrow) * ASTR_W
                                  + 4 * lksel) * 4;
        }

        load_B(j0, 0, 0);

        for (int kc = 0; kc < NKC; kc++) {
            if (kc + 1 < NKC) {
                load_B(j0, kc + 1, (kc + 1) & 1);
                asm volatile("cp.async.wait_group 1;" ::: "memory");
            } else {
                asm volatile("cp.async.wait_group 0;" ::: "memory");
            }
            if (kc == 0) {
                sqnT[tid] = g_sqn[j0 + tid];    // prev epilogue readers done
                labT[tid] = g_lab[j0 + tid];    // (trailing sync of prev tile)
            }
            __syncthreads();

            if (kc == 0) {
                #pragma unroll
                for (int mf = 0; mf < 4; mf++)
                    #pragma unroll
                    for (int nf = 0; nf < 8; nf++)
                        #pragma unroll
                        for (int q = 0; q < 4; q++) acc[mf][nf][q] = 0.f;
            }

            const uint32_t aOff = (uint32_t)kc * 128u;    // kc*32 words *4B
            const uint32_t bOff = (uint32_t)(kc & 1) * B_STAGE_BYTES;

            #pragma unroll
            for (int ks = 0; ks < 4; ks++) {              // 4 x k16 = BK
                const uint32_t kB = (uint32_t)ks * 32u;
                uint32_t af[4][4], bf[8][2];
                #pragma unroll
                for (int mf = 0; mf < 4; mf++)
                    ldsm4(af[mf], aAddr[mf] + aOff + kB);
                #pragma unroll
                for (int f = 0; f < 4; f++) {
                    uint32_t t4[4];
                    ldsm4(t4, bAddr[f] + bOff + kB);
                    bf[2*f  ][0] = t4[0]; bf[2*f+1][0] = t4[1];
                    bf[2*f  ][1] = t4[2]; bf[2*f+1][1] = t4[3];
                }
                #pragma unroll
                for (int mf = 0; mf < 4; mf++)
                    #pragma unroll
                    for (int nf = 0; nf < 8; nf++)
                        mma_fp16(acc[mf][nf], af[mf], bf[nf]);
            }

            if (kc == NKC - 1) {
                // ---- two-sided mining epilogue ----
                const float INF = __int_as_float(0x7f800000);
                float hpr[4][2], hnr[4][2];
                #pragma unroll
                for (int mf = 0; mf < 4; mf++)
                    #pragma unroll
                    for (int rh = 0; rh < 2; rh++) {
                        hpr[mf][rh] = -1.0f; hnr[mf][rh] = INF;
                    }
                #pragma unroll
                for (int nf = 0; nf < 8; nf++) {
                    const int jl  = wc * 64 + nf * 8 + qcol * 2;
                    const int jg0 = j0 + jl, jg1 = jg0 + 1;
                    const float sqj0 = sqnT[jl], sqj1 = sqnT[jl + 1];
                    const int   lj0  = labT[jl], lj1  = labT[jl + 1];
                    float hpc0 = -1.f, hnc0 = INF, hpc1 = -1.f, hnc1 = INF;
                    #pragma unroll
                    for (int mf = 0; mf < 4; mf++)
                        #pragma unroll
                        for (int rh = 0; rh < 2; rh++) {
                            const int irow = i0 + wr * 64 + mf * 16
                                             + qrow + rh * 8;
                            float d20 = fmaxf(fmaf(-2.f, acc[mf][nf][rh*2+0],
                                                   sqi[mf][rh] + sqj0), 0.f);
                            float d21 = fmaxf(fmaf(-2.f, acc[mf][nf][rh*2+1],
                                                   sqi[mf][rh] + sqj1), 0.f);
                            if (lj0 == li[mf][rh]) {
                                if (jg0 != irow) {
                                    hpr[mf][rh] = fmaxf(hpr[mf][rh], d20);
                                    hpc0 = fmaxf(hpc0, d20);
                                }
                            } else {
                                hnr[mf][rh] = fminf(hnr[mf][rh], d20);
                                hnc0 = fminf(hnc0, d20);
                            }
                            if (lj1 == li[mf][rh]) {
                                if (jg1 != irow) {
                                    hpr[mf][rh] = fmaxf(hpr[mf][rh], d21);
                                    hpc1 = fmaxf(hpc1, d21);
                                }
                            } else {
                                hnr[mf][rh] = fminf(hnr[mf][rh], d21);
                                hnc1 = fminf(hnc1, d21);
                            }
                        }
                    // column-side reduce across qrow lanes
                    #pragma unroll
                    for (int off = 4; off <= 16; off <<= 1) {
                        hpc0 = fmaxf(hpc0, __shfl_xor_sync(0xffffffffu, hpc0, off));
                        hnc0 = fminf(hnc0, __shfl_xor_sync(0xffffffffu, hnc0, off));
                        hpc1 = fmaxf(hpc1, __shfl_xor_sync(0xffffffffu, hpc1, off));
                        hnc1 = fminf(hnc1, __shfl_xor_sync(0xffffffffu, hnc1, off));
                    }
                    if (qrow == 0) {
                        atomicMax(&g_hp2[jg0], __float_as_int(hpc0));
                        atomicMin(&g_hn2[jg0], __float_as_int(hnc0));
                        atomicMax(&g_hp2[jg1], __float_as_int(hpc1));
                        atomicMin(&g_hn2[jg1], __float_as_int(hnc1));
                    }
                }
                // row-side reduce across qcol lanes
                #pragma unroll
                for (int mf = 0; mf < 4; mf++)
                    #pragma unroll
                    for (int rh = 0; rh < 2; rh++) {
                        float hp = hpr[mf][rh], hn = hnr[mf][rh];
                        hp = fmaxf(hp, __shfl_xor_sync(0xffffffffu, hp, 1));
                        hp = fmaxf(hp, __shfl_xor_sync(0xffffffffu, hp, 2));
                        hn = fminf(hn, __shfl_xor_sync(0xffffffffu, hn, 1));
                        hn = fminf(hn, __shfl_xor_sync(0xffffffffu, hn, 2));
                        if (qcol == 0) {
                            int r = i0 + wr * 64 + mf * 16 + qrow + rh * 8;
                            atomicMax(&g_hp2[r], __float_as_int(hp));
                            atomicMin(&g_hn2[r], __float_as_int(hn));
                        }
                    }
            }
            __syncthreads();
        }

        // advance to next tile (ib-major order keeps A resident)
        jt++;
        if (jt == NJT) { ib++; jt = ib >> 1; }
    }
}

// ---------------------------------------------------------------------------
// Final reduce: per-row loss, masked mean.
// ---------------------------------------------------------------------------
__global__ void reduce_kernel(float* __restrict__ out) {
    __shared__ float ss[1024];
    __shared__ int   sc[1024];
    const int t = threadIdx.x;
    float lsum = 0.f; int lcnt = 0;
    for (int r = t; r < BATCH; r += 1024) {
        int hp = g_hp2[r], hn = g_hn2[r];
        if (hp >= 0 && hn < 0x7f800000) {
            float l = sqrtf(__int_as_float(hp) + 1e-16f)
                    - sqrtf(__int_as_float(hn) + 1e-16f) + MARGIN_F;
            lsum += fmaxf(l, 0.f);
            lcnt += 1;
        }
    }
    ss[t] = lsum; sc[t] = lcnt;
    __syncthreads();
    for (int o = 512; o; o >>= 1) {
        if (t < o) { ss[t] += ss[t + o]; sc[t] += sc[t + o]; }
        __syncthreads();
    }
    if (t == 0) out[0] = ss[0] / fmaxf((float)sc[0], 1.f);
}

extern "C" void kernel_launch(void* const* d_in, const int* in_sizes, int n_in,
                              void* d_out, int out_size) {
    const float* x   = (const float*)d_in[0];
    const int*   lab = (const int*)d_in[1];   // JAX x64-disabled: int32 labels
    float*       out = (float*)d_out;

    static int nsm = 0;
    if (nsm == 0) {
        int dev = 0;
        cudaGetDevice(&dev);
        if (cudaDeviceGetAttribute(&nsm, cudaDevAttrMultiProcessorCount, dev)
            != cudaSuccess || nsm < 1 || nsm > NTILES)
            nsm = 148;
    }

    cudaFuncSetAttribute(triplet_sym,
                         cudaFuncAttributeMaxDynamicSharedMemorySize, SMEM_BYTES);

    prep_kernel<<<BATCH / 16, 256>>>(x, lab);   // 2 rows/warp, MLP=8
    triplet_sym<<<nsm, 256, SMEM_BYTES>>>();
    reduce_kernel<<<1, 1024>>>(out);
}